// round 6
// baseline (speedup 1.0000x reference)
#include <cuda_runtime.h>
#include <cstdint>

#define NV 23
#define NN 529          // 23*23
#define TV 12
#define ROWLEN 6348     // N*N*T floats per batch
#define NTHREADS 544    // 17 warps; threads 529..543 idle but sync
#define NBLOCKS 296     // 148 SMs * 2 blocks
#define CHUNK 4         // batches per cp.async group / per barrier
#define STAGES 4        // ring depth: 3 chunks (12 batches) issued ahead

__global__ __launch_bounds__(NTHREADS, 2)
void gat_kernel(const float* __restrict__ flow,
                const int*   __restrict__ adj,
                const float* __restrict__ W,
                float*       __restrict__ out,
                int B)
{
    __shared__ float dbuf[STAGES][CHUNK][NN];  // staged slices d[m*23+i]
    __shared__ int   adj_s[NN];

    const int tid = threadIdx.x;
    const bool act = (tid < NN);
    int i_idx = 0, k_idx = 0;
    if (act) { i_idx = tid / NV; k_idx = tid - i_idx * NV; }

    const uint32_t sbase = (uint32_t)__cvta_generic_to_shared(&dbuf[0][0][0]);
    const uint32_t my_dst0 = sbase + (uint32_t)tid * 4u;
    const float* my_src0 = flow + tid * TV + (TV - 1);   // gather point, batch 0

    // one chunk = CHUNK cp.asyncs per active thread + one commit (all threads)
    auto issue_chunk = [&](int s, int base) {
        if (act) {
            #pragma unroll
            for (int c = 0; c < CHUNK; ++c) {
                int b = base + c;
                const float* src = my_src0 + (size_t)(b < B ? b : 0) * ROWLEN;
                uint32_t dst = my_dst0 + (uint32_t)((s * CHUNK + c) * NN) * 4u;
                asm volatile("cp.async.ca.shared.global [%0], [%1], 4;\n"
                             :: "r"(dst), "l"(src));
            }
        }
        asm volatile("cp.async.commit_group;\n" ::: "memory");
    };

    // ---- adjacency with forced self-loops ----
    if (act) {
        int a = adj[tid];
        if (i_idx == k_idx) a = 1;
        adj_s[tid] = a;
    }

    // ---- start DRAM streaming immediately: prologue stages 0..S-2 ----
    const int step    = gridDim.x * CHUNK;
    const int myfirst = blockIdx.x * CHUNK;
    #pragma unroll
    for (int s = 0; s < STAGES - 1; ++s)
        issue_chunk(s, myfirst + s * step);

    __syncthreads();   // adj_s visible

    // ---- per-thread attention row att[i_idx][k_idx][0..22] (overlaps prologue loads) ----
    float att[NV];
    if (act) {
        const float* wr = W + tid * NV;
        float mn = 0.0f;                       // = min(min_m W, 0)
        #pragma unroll
        for (int m = 0; m < NV; ++m) {
            att[m] = wr[m];
            mn = fminf(mn, att[m]);
        }
        float s = 0.0f;
        #pragma unroll
        for (int m = 0; m < NV; ++m) {
            float a = (adj_s[k_idx * NV + m] != 0) ? (att[m] - mn) : 0.0f;
            att[m] = a;
            s += a;
        }
        float inv = 1.0f / s;
        #pragma unroll
        for (int m = 0; m < NV; ++m) att[m] *= inv;
    }

    // ---- main loop: wait 3-chunks-old group, refill, compute ----
    int it = 0;
    for (int base = myfirst; base < B; base += step, ++it) {
        const int p = it & (STAGES - 1);

        // oldest outstanding group (this stage) must be complete
        asm volatile("cp.async.wait_group %0;\n" :: "n"(STAGES - 2) : "memory");
        __syncthreads();   // data visible; previous compute on reused stage done

        // refill the stage we finished last iteration, 3 chunks ahead
        issue_chunk((it + STAGES - 1) & (STAGES - 1), base + (STAGES - 1) * step);

        if (act) {
            #pragma unroll
            for (int c = 0; c < CHUNK; ++c) {
                const int b = base + c;
                if (b < B) {
                    const float* d = dbuf[p][c];
                    float acc = 0.0f;
                    #pragma unroll
                    for (int m = 0; m < NV; ++m)
                        acc = fmaf(att[m], d[m * NV + i_idx], acc);
                    out[(size_t)b * NN + tid] = acc;   // coalesced
                }
            }
        }
    }
}

extern "C" void kernel_launch(void* const* d_in, const int* in_sizes, int n_in,
                              void* d_out, int out_size) {
    const float* flow = (const float*)d_in[0];   // (B, N, N, T) fp32
    const int*   adj  = (const int*)  d_in[1];   // (N, N) int32
    const float* W    = (const float*)d_in[2];   // (N, N, N) fp32
    float*       out  = (float*)d_out;           // (B, N, N, 1) fp32

    const int B = in_sizes[0] / ROWLEN;
    gat_kernel<<<NBLOCKS, NTHREADS>>>(flow, adj, W, out, B);
}